// round 16
// baseline (speedup 1.0000x reference)
#include <cuda_runtime.h>

#define B_      16
#define CL_     512
#define N_      3136
#define NV_     (N_ / 4)        // 784 float4 per row
#define V4T     64              // float4 columns per tile (pass 1)
#define TILES_R 13              // ceil(784 / 64)
#define NCHUNK  4               // c-chunks across blocks (measured best)
#define CCHUNK  (CL_ / NCHUNK)  // 128 c per chunk
#define CSUB    (CCHUNK / 4)    // 32 c per intra-block group
#define NPART   (NCHUNK * TILES_R)  // 52 t-partials per b

// Scratch (__device__ globals — allocation-free rule)
__device__ float4 d_g4p[NCHUNK * B_ * NV_];   // per-chunk partial g (~800 KB)
__device__ float4 d_g4[B_ * NV_];             // folded g (~200 KB)
__device__ float  d_part[B_ * NPART];         // per-(chunk,tile) partial sums of t
__device__ float  d_mt[B_];                   // mean(t) per batch

// Pass 1 (measured floor, R5-identical): grid (13, 16, 4) x 256 threads.
__global__ __launch_bounds__(256) void reduce_kernel(
    const float* __restrict__ x,
    const float* __restrict__ theta_w,
    const float* __restrict__ g_w)
{
    __shared__ float  s_tw[CCHUNK];
    __shared__ float  s_gw[CCHUNK];
    __shared__ float4 s_g[256];
    __shared__ float  s_warp[8];

    const int tile  = blockIdx.x;
    const int b     = blockIdx.y;
    const int chunk = blockIdx.z;
    const int gr    = threadIdx.x >> 6;          // 0..3
    const int ln    = threadIdx.x & 63;          // 0..63
    const int n4    = tile * V4T + ln;
    const bool valid = (n4 < NV_);
    const int cbase = chunk * CCHUNK;

    if (threadIdx.x < CCHUNK) {
        s_tw[threadIdx.x] = theta_w[cbase + threadIdx.x];
        s_gw[threadIdx.x] = g_w[cbase + threadIdx.x];
    }
    __syncthreads();

    const float4* x4 = reinterpret_cast<const float4*>(x) + (size_t)b * CL_ * NV_;

    float  t  = 0.0f;
    float4 g4 = make_float4(0.f, 0.f, 0.f, 0.f);

    if (valid) {
        const int cl0 = gr * CSUB;
        const float4* xp = x4 + (size_t)(cbase + cl0) * NV_ + n4;
        #pragma unroll 8
        for (int c = 0; c < CSUB; c++) {
            float4 v  = __ldg(xp + (size_t)c * NV_);
            float  tw = s_tw[cl0 + c];
            float  gw = s_gw[cl0 + c];
            t = fmaf((v.x + v.y) + (v.z + v.w), tw, t);
            g4.x = fmaf(v.x, gw, g4.x);
            g4.y = fmaf(v.y, gw, g4.y);
            g4.z = fmaf(v.z, gw, g4.z);
            g4.w = fmaf(v.w, gw, g4.w);
        }
    }

    // combine g across the 4 intra-block c-groups
    s_g[threadIdx.x] = g4;
    __syncthreads();
    if (threadIdx.x < V4T && valid) {
        float4 a  = s_g[threadIdx.x];
        float4 bb = s_g[threadIdx.x + 64];
        float4 cc = s_g[threadIdx.x + 128];
        float4 dd = s_g[threadIdx.x + 192];
        float4 o;
        o.x = (a.x + bb.x) + (cc.x + dd.x);
        o.y = (a.y + bb.y) + (cc.y + dd.y);
        o.z = (a.z + bb.z) + (cc.z + dd.z);
        o.w = (a.w + bb.w) + (cc.w + dd.w);
        d_g4p[(chunk * B_ + b) * NV_ + n4] = o;
    }

    // reduce t across the block -> one partial
    #pragma unroll
    for (int off = 16; off > 0; off >>= 1)
        t += __shfl_down_sync(0xFFFFFFFFu, t, off);
    if ((threadIdx.x & 31) == 0) s_warp[threadIdx.x >> 5] = t;
    __syncthreads();
    if (threadIdx.x == 0) {
        float s = 0.0f;
        #pragma unroll
        for (int w = 0; w < 8; w++) s += s_warp[w];
        d_part[b * NPART + chunk * TILES_R + tile] = s;
    }
}

// Fold: collapse 4 per-chunk g partials into d_g4 (2 elements/thread, guarded),
// and finish the t mean. grid 25 x 256.
__global__ __launch_bounds__(256) void fold_kernel()
{
    const int i0 = (blockIdx.x * blockDim.x + threadIdx.x) * 2;
    const int stride = B_ * NV_;

    #pragma unroll
    for (int e = 0; e < 2; e++) {
        const int i = i0 + e;
        if (i < B_ * NV_) {
            float4 p0 = d_g4p[i];
            float4 p1 = d_g4p[i + stride];
            float4 p2 = d_g4p[i + 2 * stride];
            float4 p3 = d_g4p[i + 3 * stride];
            float4 o;
            o.x = (p0.x + p1.x) + (p2.x + p3.x);
            o.y = (p0.y + p1.y) + (p2.y + p3.y);
            o.z = (p0.z + p1.z) + (p2.z + p3.z);
            o.w = (p0.w + p1.w) + (p2.w + p3.w);
            d_g4[i] = o;
        }
    }

    if (blockIdx.x == 0 && threadIdx.x < B_) {
        float s = 0.0f;
        #pragma unroll
        for (int k = 0; k < NPART; k++) s += d_part[threadIdx.x * NPART + k];
        d_mt[threadIdx.x] = s * (1.0f / (float)N_);
    }
}

// Pass 2: 2 adjacent vec4 (32 B) per thread — half the index math and block
// count, 2-deep load/store ILP. Pairs never straddle rows (NV_ even), so one
// (b,c) computation per thread. Reverse traversal for L2 reuse of x.
__global__ __launch_bounds__(256) void out_kernel(
    const float* __restrict__ x,
    const float* __restrict__ h_w,
    const float* __restrict__ h_b,
    float* __restrict__ out)
{
    const int totalPairs = (B_ * CL_ * NV_) / 2;           // 3,211,264
    const int p = totalPairs - 1 - (blockIdx.x * blockDim.x + threadIdx.x);
    const int v = p * 2;                                   // first vec4 of the pair

    const int n4  = v % NV_;          // pair stays in-row: n4, n4+1
    const int row = v / NV_;          // row = b*CL + c
    const int c   = row % CL_;
    const int b   = row / CL_;

    const float mt  = __ldg(&d_mt[b]);      // uniform per block -> L1 hit
    const float hwc = h_w[c] * mt;
    const float hbc = h_b[c];

    const float4* xr = reinterpret_cast<const float4*>(x) + v;
    float4*      orr = reinterpret_cast<float4*>(out) + v;
    const float4* gp = &d_g4[b * NV_ + n4];

    const float4 xa = __ldcs(xr);           // last use of x
    const float4 xb = __ldcs(xr + 1);
    const float4 ga = gp[0];
    const float4 gb = gp[1];

    float4 oa, ob;
    oa.x = fmaf(ga.x, hwc, xa.x) + hbc;
    oa.y = fmaf(ga.y, hwc, xa.y) + hbc;
    oa.z = fmaf(ga.z, hwc, xa.z) + hbc;
    oa.w = fmaf(ga.w, hwc, xa.w) + hbc;
    ob.x = fmaf(gb.x, hwc, xb.x) + hbc;
    ob.y = fmaf(gb.y, hwc, xb.y) + hbc;
    ob.z = fmaf(gb.z, hwc, xb.z) + hbc;
    ob.w = fmaf(gb.w, hwc, xb.w) + hbc;

    __stcs(orr,     oa);                    // streaming stores
    __stcs(orr + 1, ob);
}

extern "C" void kernel_launch(void* const* d_in, const int* in_sizes, int n_in,
                              void* d_out, int out_size)
{
    const float* x       = (const float*)d_in[0];
    const float* theta_w = (const float*)d_in[1];
    const float* g_w     = (const float*)d_in[2];
    const float* h_w     = (const float*)d_in[3];
    const float* h_b     = (const float*)d_in[4];
    float*       out     = (float*)d_out;

    dim3 grid1(TILES_R, B_, NCHUNK);       // 13 x 16 x 4 = 832 blocks
    reduce_kernel<<<grid1, 256>>>(x, theta_w, g_w);

    fold_kernel<<<(B_ * NV_ + 511) / 512, 256>>>();   // 25 blocks, guarded

    const int totalPairs = (B_ * CL_ * NV_) / 2;   // 3,211,264
    out_kernel<<<totalPairs / 256, 256>>>(x, h_w, h_b, out);
}

// round 17
// speedup vs baseline: 1.0907x; 1.0907x over previous
#include <cuda_runtime.h>

#define B_      16
#define CL_     512
#define N_      3136
#define NV_     (N_ / 4)        // 784 float4 per row
#define V4T     64              // float4 columns per tile (pass 1)
#define TILES_R 13              // ceil(784 / 64)
#define NCHUNK  4               // c-chunks across blocks (measured best)
#define CCHUNK  (CL_ / NCHUNK)  // 128 c per chunk
#define CSUB    (CCHUNK / 4)    // 32 c per intra-block group
#define NPART   (NCHUNK * TILES_R)  // 52 t-partials per b
#define OUT_BLKS ((B_ * CL_ * NV_) / 2 / 256)   // 12544 blocks (32 B per thread)

// Scratch (__device__ globals — allocation-free rule)
__device__ float4 d_g4p[NCHUNK * B_ * NV_];   // per-chunk partial g (~800 KB)
__device__ float4 d_g4[B_ * NV_];             // folded g (~200 KB)
__device__ float  d_part[B_ * NPART];         // per-(chunk,tile) partial sums of t
__device__ float  d_mt[B_];                   // mean(t) per batch

// 256-bit global accessors (sm_100+): one instruction per 32 B.
__device__ __forceinline__ void ldg256_cs(const float4* p, float4& a, float4& b) {
    asm volatile("ld.global.cs.v8.b32 {%0,%1,%2,%3,%4,%5,%6,%7}, [%8];"
                 : "=f"(a.x), "=f"(a.y), "=f"(a.z), "=f"(a.w),
                   "=f"(b.x), "=f"(b.y), "=f"(b.z), "=f"(b.w)
                 : "l"(p));
}
__device__ __forceinline__ void ldg256(const float4* p, float4& a, float4& b) {
    asm volatile("ld.global.v8.b32 {%0,%1,%2,%3,%4,%5,%6,%7}, [%8];"
                 : "=f"(a.x), "=f"(a.y), "=f"(a.z), "=f"(a.w),
                   "=f"(b.x), "=f"(b.y), "=f"(b.z), "=f"(b.w)
                 : "l"(p));
}
__device__ __forceinline__ void stg256_cs(float4* p, const float4& a, const float4& b) {
    asm volatile("st.global.cs.v8.b32 [%0], {%1,%2,%3,%4,%5,%6,%7,%8};"
                 :: "l"(p),
                    "f"(a.x), "f"(a.y), "f"(a.z), "f"(a.w),
                    "f"(b.x), "f"(b.y), "f"(b.z), "f"(b.w)
                 : "memory");
}

// Pass 1 (measured floor, R5-identical): grid (13, 16, 4) x 256 threads.
__global__ __launch_bounds__(256) void reduce_kernel(
    const float* __restrict__ x,
    const float* __restrict__ theta_w,
    const float* __restrict__ g_w)
{
    __shared__ float  s_tw[CCHUNK];
    __shared__ float  s_gw[CCHUNK];
    __shared__ float4 s_g[256];
    __shared__ float  s_warp[8];

    const int tile  = blockIdx.x;
    const int b     = blockIdx.y;
    const int chunk = blockIdx.z;
    const int gr    = threadIdx.x >> 6;          // 0..3
    const int ln    = threadIdx.x & 63;          // 0..63
    const int n4    = tile * V4T + ln;
    const bool valid = (n4 < NV_);
    const int cbase = chunk * CCHUNK;

    if (threadIdx.x < CCHUNK) {
        s_tw[threadIdx.x] = theta_w[cbase + threadIdx.x];
        s_gw[threadIdx.x] = g_w[cbase + threadIdx.x];
    }
    __syncthreads();

    const float4* x4 = reinterpret_cast<const float4*>(x) + (size_t)b * CL_ * NV_;

    float  t  = 0.0f;
    float4 g4 = make_float4(0.f, 0.f, 0.f, 0.f);

    if (valid) {
        const int cl0 = gr * CSUB;
        const float4* xp = x4 + (size_t)(cbase + cl0) * NV_ + n4;
        #pragma unroll 8
        for (int c = 0; c < CSUB; c++) {
            float4 v  = __ldg(xp + (size_t)c * NV_);
            float  tw = s_tw[cl0 + c];
            float  gw = s_gw[cl0 + c];
            t = fmaf((v.x + v.y) + (v.z + v.w), tw, t);
            g4.x = fmaf(v.x, gw, g4.x);
            g4.y = fmaf(v.y, gw, g4.y);
            g4.z = fmaf(v.z, gw, g4.z);
            g4.w = fmaf(v.w, gw, g4.w);
        }
    }

    // combine g across the 4 intra-block c-groups
    s_g[threadIdx.x] = g4;
    __syncthreads();
    if (threadIdx.x < V4T && valid) {
        float4 a  = s_g[threadIdx.x];
        float4 bb = s_g[threadIdx.x + 64];
        float4 cc = s_g[threadIdx.x + 128];
        float4 dd = s_g[threadIdx.x + 192];
        float4 o;
        o.x = (a.x + bb.x) + (cc.x + dd.x);
        o.y = (a.y + bb.y) + (cc.y + dd.y);
        o.z = (a.z + bb.z) + (cc.z + dd.z);
        o.w = (a.w + bb.w) + (cc.w + dd.w);
        d_g4p[(chunk * B_ + b) * NV_ + n4] = o;
    }

    // reduce t across the block -> one partial
    #pragma unroll
    for (int off = 16; off > 0; off >>= 1)
        t += __shfl_down_sync(0xFFFFFFFFu, t, off);
    if ((threadIdx.x & 31) == 0) s_warp[threadIdx.x >> 5] = t;
    __syncthreads();
    if (threadIdx.x == 0) {
        float s = 0.0f;
        #pragma unroll
        for (int w = 0; w < 8; w++) s += s_warp[w];
        d_part[b * NPART + chunk * TILES_R + tile] = s;
    }
}

// Fold (R5-identical): collapse 4 per-chunk g partials into d_g4, finish mt.
__global__ __launch_bounds__(256) void fold_kernel()
{
    const int i = blockIdx.x * blockDim.x + threadIdx.x;   // 0 .. B_*NV_-1
    const int stride = B_ * NV_;

    float4 p0 = d_g4p[i];
    float4 p1 = d_g4p[i + stride];
    float4 p2 = d_g4p[i + 2 * stride];
    float4 p3 = d_g4p[i + 3 * stride];
    float4 o;
    o.x = (p0.x + p1.x) + (p2.x + p3.x);
    o.y = (p0.y + p1.y) + (p2.y + p3.y);
    o.z = (p0.z + p1.z) + (p2.z + p3.z);
    o.w = (p0.w + p1.w) + (p2.w + p3.w);
    d_g4[i] = o;

    if (blockIdx.x == 0 && threadIdx.x < B_) {
        float s = 0.0f;
        #pragma unroll
        for (int k = 0; k < NPART; k++) s += d_part[threadIdx.x * NPART + k];
        d_mt[threadIdx.x] = s * (1.0f / (float)N_);
    }
}

// Pass 2: 32 B per thread via 256-bit ld/st (one LDG.256 + one STG.256 for x/out).
// Block-REVERSED, thread-FORWARD: warps access perfectly contiguous 1 KB spans
// while the global sweep still runs tail-first for L2 reuse of x.
__global__ __launch_bounds__(256) void out_kernel(
    const float* __restrict__ x,
    const float* __restrict__ h_w,
    const float* __restrict__ h_b,
    float* __restrict__ out)
{
    const int pair = (OUT_BLKS - 1 - blockIdx.x) * blockDim.x + threadIdx.x;
    const int v    = pair * 2;        // first float4 of this thread's 32 B

    const int n4  = v % NV_;          // pair stays in-row (NV_ even)
    const int row = v / NV_;          // row = b*CL + c
    const int c   = row & (CL_ - 1);  // CL_ = 512
    const int b   = row >> 9;

    const float mt  = __ldg(&d_mt[b]);      // uniform per block -> L1 hit
    const float hwc = h_w[c] * mt;
    const float hbc = h_b[c];

    float4 xa, xb, ga, gb;
    ldg256_cs(reinterpret_cast<const float4*>(x) + v, xa, xb);   // last use of x
    ldg256(&d_g4[b * NV_ + n4], ga, gb);                         // L2-resident

    float4 oa, ob;
    oa.x = fmaf(ga.x, hwc, xa.x) + hbc;
    oa.y = fmaf(ga.y, hwc, xa.y) + hbc;
    oa.z = fmaf(ga.z, hwc, xa.z) + hbc;
    oa.w = fmaf(ga.w, hwc, xa.w) + hbc;
    ob.x = fmaf(gb.x, hwc, xb.x) + hbc;
    ob.y = fmaf(gb.y, hwc, xb.y) + hbc;
    ob.z = fmaf(gb.z, hwc, xb.z) + hbc;
    ob.w = fmaf(gb.w, hwc, xb.w) + hbc;

    stg256_cs(reinterpret_cast<float4*>(out) + v, oa, ob);       // streaming store
}

extern "C" void kernel_launch(void* const* d_in, const int* in_sizes, int n_in,
                              void* d_out, int out_size)
{
    const float* x       = (const float*)d_in[0];
    const float* theta_w = (const float*)d_in[1];
    const float* g_w     = (const float*)d_in[2];
    const float* h_w     = (const float*)d_in[3];
    const float* h_b     = (const float*)d_in[4];
    float*       out     = (float*)d_out;

    dim3 grid1(TILES_R, B_, NCHUNK);       // 13 x 16 x 4 = 832 blocks
    reduce_kernel<<<grid1, 256>>>(x, theta_w, g_w);

    fold_kernel<<<(B_ * NV_) / 256, 256>>>();   // 49 blocks

    out_kernel<<<OUT_BLKS, 256>>>(x, h_w, h_b, out);   // 12544 blocks
}